// round 15
// baseline (speedup 1.0000x reference)
#include <cuda_runtime.h>
#include <cuda_fp16.h>
#include <cstdint>
#include <math.h>

#define DN 16384
#define DL 10
#define DD 256
#define NCHUNK 4
#define CHUNK (DN / NCHUNK)     // 4096

// ======================= helpers =======================

__device__ __forceinline__ uint32_t smem_u32(const void* p) {
    uint32_t a;
    asm("{ .reg .u64 t; cvta.to.shared.u64 t, %1; cvt.u32.u64 %0, t; }" : "=r"(a) : "l"(p));
    return a;
}

__device__ __forceinline__ void ldsm4(uint32_t* r, uint32_t a) {
    asm volatile("ldmatrix.sync.aligned.m8n8.x4.shared.b16 {%0,%1,%2,%3}, [%4];"
                 : "=r"(r[0]), "=r"(r[1]), "=r"(r[2]), "=r"(r[3]) : "r"(a));
}

__device__ __forceinline__ void mma16816(float* c, const uint32_t* a, uint32_t b0, uint32_t b1) {
    asm volatile("mma.sync.aligned.m16n8k16.row.col.f32.f16.f16.f32 "
                 "{%0,%1,%2,%3}, {%4,%5,%6,%7}, {%8,%9}, {%0,%1,%2,%3};"
                 : "+f"(c[0]), "+f"(c[1]), "+f"(c[2]), "+f"(c[3])
                 : "r"(a[0]), "r"(a[1]), "r"(a[2]), "r"(a[3]), "r"(b0), "r"(b1));
}

__device__ __forceinline__ void cp16(uint32_t s, const void* g) {
    asm volatile("cp.async.cg.shared.global [%0], [%1], 16;" :: "r"(s), "l"(g) : "memory");
}

// ======================= globals (scratch) =======================

__device__ __align__(16) float g_r[2 * DD];
__device__ __align__(16) float g_bo[DD];

__device__ __align__(16) __half g_Gt[2 * DD * DD];   // [512][256] (n-major, k contig)
__device__ __align__(16) __half g_Wt[DD * 2 * DD];   // [256][512]
__device__ __align__(16) __half g_M[(size_t)DN * DD];        // m_last fp16
__device__ __align__(16) __half g_U[(size_t)DN * 2 * DD];    // U fp16

// ======================= precompute, split by consumer =======================

__global__ void __launch_bounds__(256) prep_g(
    const float* __restrict__ w_in, const float* __restrict__ b_in,
    const float* __restrict__ msgs)
{
    __shared__ float sbuf[512];
    const int b = blockIdx.x;
    const int t = threadIdx.x;

    if (b < 256) {
        const int k0 = b * 2;
        const int h  = k0 >> 8;
        const int d0 = k0 & 255;
        {
            int j = t >> 1, dd = t & 1;
            sbuf[j * 2 + dd] = w_in[(size_t)(DD + h * 128 + j) * DD + d0 + dd];
        }
        __syncthreads();
        const int e = t;
        float a0 = 0.f, a1 = 0.f;
        const float* wq = w_in + (size_t)(h * 128) * DD + e;
#pragma unroll 4
        for (int j = 0; j < 128; j++) {
            float q = wq[(size_t)j * DD];
            a0 = fmaf(q, sbuf[j * 2 + 0], a0);
            a1 = fmaf(q, sbuf[j * 2 + 1], a1);
        }
        g_Gt[(size_t)(k0 + 0) * DD + e] = __float2half_rn(a0);
        g_Gt[(size_t)(k0 + 1) * DD + e] = __float2half_rn(a1);
    } else if (b < 258) {
        int h = b - 256, d = t;
        float a = 0.f;
        for (int j = 0; j < 128; j++)
            a = fmaf(w_in[(size_t)(DD + h * 128 + j) * DD + d], b_in[h * 128 + j], a);
        g_r[h * DD + d] = a;
    } else {
        int idx = (b - 258) * 256 + t;
        int n = idx >> 5, d8 = (idx & 31) * 8;
        const float* gp = msgs + ((size_t)n * DL + (DL - 1)) * DD + d8;
        float4 v0 = *reinterpret_cast<const float4*>(gp);
        float4 v1 = *reinterpret_cast<const float4*>(gp + 4);
        __half2 hh[4];
        hh[0] = __floats2half2_rn(v0.x, v0.y); hh[1] = __floats2half2_rn(v0.z, v0.w);
        hh[2] = __floats2half2_rn(v1.x, v1.y); hh[3] = __floats2half2_rn(v1.z, v1.w);
        *reinterpret_cast<uint4*>(&g_M[(size_t)n * DD + d8]) = *reinterpret_cast<uint4*>(hh);
    }
}

__global__ void __launch_bounds__(256) prep_w(
    const float* __restrict__ w_in, const float* __restrict__ b_in,
    const float* __restrict__ w_out, const float* __restrict__ b_out)
{
    __shared__ float sbuf[256];
    const int b = blockIdx.x;
    const int t = threadIdx.x;

    if (b < 512) {
        const int d = b >> 1;
        const int rep = b & 1;
        if (t < DD) sbuf[t] = w_out[(size_t)d * DD + t];
        __syncthreads();
        const int k = rep * 256 + t;
        const int h = rep, e = t;
        const float* wv  = w_in + (size_t)(2 * DD + h * 128) * DD + e;
        const float* wor = sbuf + h * 128;
        float acc = 0.f;
#pragma unroll 8
        for (int j = 0; j < 128; j++)
            acc = fmaf(wor[j], wv[(size_t)j * DD], acc);
        g_Wt[(size_t)d * 512 + k] = __float2half_rn(acc);
    } else {
        float a = b_out[t];
        for (int c = 0; c < DD; c++)
            a = fmaf(w_out[(size_t)t * DD + c], b_in[2 * DD + c], a);
        g_bo[t] = a;
    }
}

// ======================= gemm1 (unchanged, proven) =======================

#define SM_ROW 144
#define SM_BUF 18432             // 128*144
#define STAGE  (2 * SM_BUF)      // 36864 (A, B)
#define GEMM_SMEM (3 * STAGE)    // 110592

__global__ void __launch_bounds__(256, 2) gemm1_k(int m_base) {
    extern __shared__ char sm[];
    const int tid = threadIdx.x, lane = tid & 31, wid = tid >> 5;
    const int m0 = m_base + blockIdx.x * 128, n0 = blockIdx.y * 128;
    const int wm = (wid >> 2) * 64, wn = (wid & 3) * 32;
    const uint32_t sbase = smem_u32(sm);
    const __half* A = g_M;
    const __half* B = g_Gt;
    constexpr int KT = DD;

    float acc[4][4][4];
#pragma unroll
    for (int a = 0; a < 4; a++)
#pragma unroll
        for (int bq = 0; bq < 4; bq++)
#pragma unroll
            for (int cc = 0; cc < 4; cc++) acc[a][bq][cc] = 0.f;

#define LOAD_ITER(st, k0c, it) do { \
        uint32_t s0 = sbase + (st) * STAGE; \
        int idx = tid + (it) * 256; \
        int r = idx >> 3, q = idx & 7; \
        uint32_t so = (uint32_t)(r * SM_ROW + q * 16); \
        size_t ga = (size_t)(m0 + r) * KT + (k0c) + q * 8; \
        size_t gb = (size_t)(n0 + r) * KT + (k0c) + q * 8; \
        cp16(s0 + so, A + ga); \
        cp16(s0 + SM_BUF + so, B + gb); \
    } while (0)

#define LOAD_STAGE(st, k0c) do { \
        LOAD_ITER(st, k0c, 0); LOAD_ITER(st, k0c, 1); \
        LOAD_ITER(st, k0c, 2); LOAD_ITER(st, k0c, 3); \
        asm volatile("cp.async.commit_group;" ::: "memory"); \
    } while (0)

    const int NC = KT / 64;
    LOAD_STAGE(0, 0);
    LOAD_STAGE(1, 64);
    for (int c = 0; c < NC; c++) {
        asm volatile("cp.async.wait_group 1;" ::: "memory");
        __syncthreads();

        const uint32_t uA = sbase + (c % 3) * STAGE;
        const uint32_t uB = uA + SM_BUF;
        const bool do_load = (c + 2 < NC);
        const int  nst = (c + 2) % 3;
        const int  nk0 = (c + 2) * 64;

#pragma unroll
        for (int kk = 0; kk < 4; kk++) {
            const uint32_t colb = (uint32_t)(kk * 32 + (lane >> 4) * 16);
            const uint32_t arow = (uint32_t)(wm + (lane & 15));
            uint32_t af[4][4], bf[2][4];
#pragma unroll
            for (int nt = 0; nt < 2; nt++) {
                uint32_t brow = (uint32_t)(wn + nt * 16 + (lane & 15));
                ldsm4(bf[nt], uB + brow * SM_ROW + colb);
            }
#pragma unroll
            for (int mt = 0; mt < 4; mt++)
                ldsm4(af[mt], uA + (arow + mt * 16) * SM_ROW + colb);
            if (do_load) LOAD_ITER(nst, nk0, kk);
#pragma unroll
            for (int mt = 0; mt < 4; mt++)
#pragma unroll
                for (int ns = 0; ns < 4; ns++)
                    mma16816(acc[mt][ns], af[mt], bf[ns >> 1][ns & 1], bf[ns >> 1][(ns & 1) + 2]);
        }
        asm volatile("cp.async.commit_group;" ::: "memory");
    }
#undef LOAD_STAGE
#undef LOAD_ITER

#pragma unroll
    for (int mt = 0; mt < 4; mt++) {
        int r0 = m0 + wm + mt * 16 + (lane >> 2);
#pragma unroll
        for (int ns = 0; ns < 4; ns++) {
            int cx = n0 + wn + ns * 8 + (lane & 3) * 2;
            float2 bb = *reinterpret_cast<const float2*>(g_r + cx);
            *reinterpret_cast<__half2*>(g_U + (size_t)r0 * 512 + cx) =
                __floats2half2_rn(acc[mt][ns][0] + bb.x, acc[mt][ns][1] + bb.y);
            *reinterpret_cast<__half2*>(g_U + (size_t)(r0 + 8) * 512 + cx) =
                __floats2half2_rn(acc[mt][ns][2] + bb.x, acc[mt][ns][3] + bb.y);
        }
    }
}

// ======================= mega2: score+agg (smem Mb) + gemm2 =======================
// 512 threads, grid CHUNK/128 per chunk; CTA covers 128 seqs x 256 out cols.
// Phase A: warp w computes seqs w*8..w*8+7, writes Mb fp16 rows into smem (pitch 1040).
// Phase B: C = Mb(smem) @ Wt^T, B staged via cp.async (k-chunk 32, 3 stages, pitch 80).

#define U_PITCH   1040
#define A_BYTES   (128 * U_PITCH)            // 133120
#define B_STG     (256 * 80)                 // 20480
#define MEGA2_SMEM (A_BYTES + 3 * B_STG)     // 194560

__global__ void __launch_bounds__(512, 1) mega2(
    const float* __restrict__ msgs, const float* __restrict__ tstamp,
    const float* __restrict__ w_time, const float* __restrict__ b_time,
    const int* __restrict__ lengths, float* __restrict__ out, int m_base)
{
    extern __shared__ char sm[];
    const int tid = threadIdx.x, lane = tid & 31, wid = tid >> 5;
    const int m0 = m_base + blockIdx.x * 128;
    const uint32_t uA   = smem_u32(sm);
    const uint32_t uStg = uA + A_BYTES;

    const int wm = (wid >> 3) * 64;      // 2 m-groups of 64
    const int wn = (wid & 7) * 32;       // 8 n-groups of 32

#define B_LOAD(st, k0c) do { \
        uint32_t s0 = uStg + (st) * B_STG; \
        _Pragma("unroll") \
        for (int it = 0; it < 2; it++) { \
            int idx = tid + it * 512; \
            int r = idx >> 2, q = idx & 3; \
            cp16(s0 + r * 80 + q * 16, g_Wt + (size_t)r * 512 + (k0c) + q * 8); \
        } \
        asm volatile("cp.async.commit_group;" ::: "memory"); \
    } while (0)

    // prefetch first two B stages (hidden under phase A's msgs stream)
    B_LOAD(0, 0);
    B_LOAD(1, 32);

    // ---------- phase A: scores + softmax + aggregate -> smem Mb ----------
    {
        const int e8 = lane * 8;
        float wt[8], bt[8];
        {
            float4 wa = *reinterpret_cast<const float4*>(w_time + e8);
            float4 wb = *reinterpret_cast<const float4*>(w_time + e8 + 4);
            float4 ba = *reinterpret_cast<const float4*>(b_time + e8);
            float4 bb = *reinterpret_cast<const float4*>(b_time + e8 + 4);
            wt[0]=wa.x; wt[1]=wa.y; wt[2]=wa.z; wt[3]=wa.w;
            wt[4]=wb.x; wt[5]=wb.y; wt[6]=wb.z; wt[7]=wb.w;
            bt[0]=ba.x; bt[1]=ba.y; bt[2]=ba.z; bt[3]=ba.w;
            bt[4]=bb.x; bt[5]=bb.y; bt[6]=bb.z; bt[7]=bb.w;
        }
        const float scale = 0.08838834764831845f;

#pragma unroll 1
        for (int i = 0; i < 8; i++) {
            const int s_loc = wid * 8 + i;
            const int s = m0 + s_loc;
            const int pad = DL - (lengths[s] + 1);

            float u0[8], u1[8];
            {
                uint4 h0 = *reinterpret_cast<const uint4*>(&g_U[(size_t)s * 512 + e8]);
                uint4 h1 = *reinterpret_cast<const uint4*>(&g_U[(size_t)s * 512 + 256 + e8]);
                const __half2* p0 = reinterpret_cast<const __half2*>(&h0);
                const __half2* p1 = reinterpret_cast<const __half2*>(&h1);
#pragma unroll
                for (int j = 0; j < 4; j++) {
                    float2 f0 = __half22float2(p0[j]);
                    float2 f1 = __half22float2(p1[j]);
                    u0[2*j] = f0.x; u0[2*j+1] = f0.y;
                    u1[2*j] = f1.x; u1[2*j+1] = f1.y;
                }
            }
            float ts9 = tstamp[(size_t)s * DL + (DL - 1)];

            float sc0[DL], sc1[DL];
#pragma unroll
            for (int l = 0; l < DL; l++) {
                if (l >= pad) {
                    float delta = tstamp[(size_t)s * DL + l] - ts9;
                    float a0 = 0.f, a1 = 0.f;
#pragma unroll
                    for (int j = 0; j < 8; j++) {
                        float te = __cosf(fmaf(delta, wt[j], bt[j]));
                        a0 = fmaf(te, u0[j], a0);
                        a1 = fmaf(te, u1[j], a1);
                    }
#pragma unroll
                    for (int o = 16; o; o >>= 1) {
                        a0 += __shfl_xor_sync(0xFFFFFFFF, a0, o);
                        a1 += __shfl_xor_sync(0xFFFFFFFF, a1, o);
                    }
                    sc0[l] = a0 * scale;
                    sc1[l] = a1 * scale;
                } else { sc0[l] = 0.f; sc1[l] = 0.f; }
            }

            float mx0 = -3.4e38f, mx1 = -3.4e38f;
#pragma unroll
            for (int l = 0; l < DL; l++) {
                if (l >= pad) { mx0 = fmaxf(mx0, sc0[l]); mx1 = fmaxf(mx1, sc1[l]); }
            }
            float sm0 = 0.f, sm1 = 0.f;
#pragma unroll
            for (int l = 0; l < DL; l++) {
                if (l >= pad) {
                    sc0[l] = __expf(sc0[l] - mx0); sm0 += sc0[l];
                    sc1[l] = __expf(sc1[l] - mx1); sm1 += sc1[l];
                }
            }
            float i0 = 1.f / sm0, i1 = 1.f / sm1;
#pragma unroll
            for (int l = 0; l < DL; l++) {
                if (l >= pad) { sc0[l] *= i0; sc1[l] *= i1; }
            }

#pragma unroll
            for (int ii = 0; ii < 2; ii++) {
                int e4 = lane * 4 + ii * 128;
                float m0a[4] = {0.f, 0.f, 0.f, 0.f};
                float m1a[4] = {0.f, 0.f, 0.f, 0.f};
                const float* mp = msgs + (size_t)s * DL * DD + e4;
#pragma unroll
                for (int l = 0; l < DL - 1; l++) {
                    if (l >= pad) {
                        float4 v = *reinterpret_cast<const float4*>(mp + (size_t)l * DD);
                        m0a[0] = fmaf(sc0[l], v.x, m0a[0]); m0a[1] = fmaf(sc0[l], v.y, m0a[1]);
                        m0a[2] = fmaf(sc0[l], v.z, m0a[2]); m0a[3] = fmaf(sc0[l], v.w, m0a[3]);
                        m1a[0] = fmaf(sc1[l], v.x, m1a[0]); m1a[1] = fmaf(sc1[l], v.y, m1a[1]);
                        m1a[2] = fmaf(sc1[l], v.z, m1a[2]); m1a[3] = fmaf(sc1[l], v.w, m1a[3]);
                    }
                }
                {
                    uint2 hm = *reinterpret_cast<const uint2*>(&g_M[(size_t)s * DD + e4]);
                    const __half2* ph = reinterpret_cast<const __half2*>(&hm);
                    float2 f0 = __half22float2(ph[0]);
                    float2 f1 = __half22float2(ph[1]);
                    float v9[4] = {f0.x, f0.y, f1.x, f1.y};
#pragma unroll
                    for (int j = 0; j < 4; j++) {
                        m0a[j] = fmaf(sc0[DL - 1], v9[j], m0a[j]);
                        m1a[j] = fmaf(sc1[DL - 1], v9[j], m1a[j]);
                    }
                }
                char* row = sm + (size_t)s_loc * U_PITCH;
                *reinterpret_cast<__half2*>(row + e4 * 2)           = __floats2half2_rn(m0a[0], m0a[1]);
                *reinterpret_cast<__half2*>(row + e4 * 2 + 4)       = __floats2half2_rn(m0a[2], m0a[3]);
                *reinterpret_cast<__half2*>(row + 512 + e4 * 2)     = __floats2half2_rn(m1a[0], m1a[1]);
                *reinterpret_cast<__half2*>(row + 512 + e4 * 2 + 4) = __floats2half2_rn(m1a[2], m1a[3]);
            }
        }
    }

    // ---------- phase B: OUT = Mb(smem) @ Wt^T ----------
    {
        float acc[4][4][4];
#pragma unroll
        for (int a = 0; a < 4; a++)
#pragma unroll
            for (int bq = 0; bq < 4; bq++)
#pragma unroll
                for (int cc = 0; cc < 4; cc++) acc[a][bq][cc] = 0.f;

#pragma unroll 1
        for (int c = 0; c < 16; c++) {
            asm volatile("cp.async.wait_group 1;" ::: "memory");
            __syncthreads();   // c==0: also the phase A -> B barrier
            if (c + 2 < 16) { B_LOAD((c + 2) % 3, (c + 2) * 32); }
            else { asm volatile("cp.async.commit_group;" ::: "memory"); }

            const uint32_t uB = uStg + (c % 3) * B_STG;
#pragma unroll
            for (int kk = 0; kk < 2; kk++) {
                const uint32_t colb = (uint32_t)(kk * 32 + (lane >> 4) * 16);
                const uint32_t ca   = (uint32_t)(c * 64) + colb;
                const uint32_t arow = (uint32_t)(wm + (lane & 15));
                uint32_t af[4][4], bf[2][4];
#pragma unroll
                for (int nt = 0; nt < 2; nt++) {
                    uint32_t brow = (uint32_t)(wn + nt * 16 + (lane & 15));
                    ldsm4(bf[nt], uB + brow * 80 + colb);
                }
#pragma unroll
                for (int mt = 0; mt < 4; mt++)
                    ldsm4(af[mt], uA + (arow + mt * 16) * U_PITCH + ca);
#pragma unroll
                for (int mt = 0; mt < 4; mt++)
#pragma unroll
                    for (int ns = 0; ns < 4; ns++)
                        mma16816(acc[mt][ns], af[mt], bf[ns >> 1][ns & 1], bf[ns >> 1][(ns & 1) + 2]);
            }
        }

#pragma unroll
        for (int mt = 0; mt < 4; mt++) {
            int r0 = m0 + wm + mt * 16 + (lane >> 2);
#pragma unroll
            for (int ns = 0; ns < 4; ns++) {
                int cx = wn + ns * 8 + (lane & 3) * 2;
                float2 bb = *reinterpret_cast<const float2*>(g_bo + cx);
                float2 v0, v1;
                v0.x = acc[mt][ns][0] + bb.x; v0.y = acc[mt][ns][1] + bb.y;
                v1.x = acc[mt][ns][2] + bb.x; v1.y = acc[mt][ns][3] + bb.y;
                *reinterpret_cast<float2*>(out + (size_t)r0 * DD + cx) = v0;
                *reinterpret_cast<float2*>(out + (size_t)(r0 + 8) * DD + cx) = v1;
            }
        }
    }
#undef B_LOAD
}

// ======================= streams (created once, pre-checkpoint) =======================

static cudaStream_t g_st[NCHUNK];
static cudaStream_t g_stW;
static cudaEvent_t  g_e0, g_eP, g_eW;
static cudaEvent_t  g_eC[NCHUNK];

namespace {
struct StreamInit {
    StreamInit() {
        for (int i = 0; i < NCHUNK; i++)
            cudaStreamCreateWithFlags(&g_st[i], cudaStreamNonBlocking);
        cudaStreamCreateWithFlags(&g_stW, cudaStreamNonBlocking);
        cudaEventCreateWithFlags(&g_e0, cudaEventDisableTiming);
        cudaEventCreateWithFlags(&g_eP, cudaEventDisableTiming);
        cudaEventCreateWithFlags(&g_eW, cudaEventDisableTiming);
        for (int i = 0; i < NCHUNK; i++)
            cudaEventCreateWithFlags(&g_eC[i], cudaEventDisableTiming);
    }
};
StreamInit g_stream_init;
}

// ======================= launch =======================

extern "C" void kernel_launch(void* const* d_in, const int* in_sizes, int n_in,
                              void* d_out, int out_size) {
    const float* msgs    = (const float*)d_in[0];
    const float* ts      = (const float*)d_in[1];
    const float* w_time  = (const float*)d_in[2];
    const float* b_time  = (const float*)d_in[3];
    const float* w_in    = (const float*)d_in[4];
    const float* b_in    = (const float*)d_in[5];
    const float* w_out   = (const float*)d_in[6];
    const float* b_out   = (const float*)d_in[7];
    const int*   lengths = (const int*)d_in[8];
    float* out = (float*)d_out;

    cudaFuncSetAttribute(gemm1_k, cudaFuncAttributeMaxDynamicSharedMemorySize, GEMM_SMEM);
    cudaFuncSetAttribute(mega2,   cudaFuncAttributeMaxDynamicSharedMemorySize, MEGA2_SMEM);

    // fork prep_w (needed only by mega2's B operand)
    cudaEventRecord(g_e0, 0);
    cudaStreamWaitEvent(g_stW, g_e0, 0);
    prep_w<<<513, 256, 0, g_stW>>>(w_in, b_in, w_out, b_out);
    cudaEventRecord(g_eW, g_stW);

    // gemm1-critical prep on the origin stream
    prep_g<<<2306, 256>>>(w_in, b_in, msgs);
    cudaEventRecord(g_eP, 0);

    for (int c = 0; c < NCHUNK; c++) {
        const int base = c * CHUNK;
        cudaStreamWaitEvent(g_st[c], g_eP, 0);
        gemm1_k<<<dim3(CHUNK / 128, 4), 256, GEMM_SMEM, g_st[c]>>>(base);
        cudaStreamWaitEvent(g_st[c], g_eW, 0);
        mega2<<<CHUNK / 128, 512, MEGA2_SMEM, g_st[c]>>>(msgs, ts, w_time, b_time, lengths, out, base);
        cudaEventRecord(g_eC[c], g_st[c]);
    }
    for (int c = 0; c < NCHUNK; c++)
        cudaStreamWaitEvent(0, g_eC[c], 0);
}

// round 16
// speedup vs baseline: 1.0526x; 1.0526x over previous
#include <cuda_runtime.h>
#include <cuda_fp16.h>
#include <cstdint>
#include <math.h>

#define DN 16384
#define DL 10
#define DD 256
#define NCHUNK 8
#define CHUNK (DN / NCHUNK)     // 2048

// ======================= helpers =======================

__device__ __forceinline__ uint32_t smem_u32(const void* p) {
    uint32_t a;
    asm("{ .reg .u64 t; cvta.to.shared.u64 t, %1; cvt.u32.u64 %0, t; }" : "=r"(a) : "l"(p));
    return a;
}

__device__ __forceinline__ void ldsm4(uint32_t* r, uint32_t a) {
    asm volatile("ldmatrix.sync.aligned.m8n8.x4.shared.b16 {%0,%1,%2,%3}, [%4];"
                 : "=r"(r[0]), "=r"(r[1]), "=r"(r[2]), "=r"(r[3]) : "r"(a));
}

__device__ __forceinline__ void mma16816(float* c, const uint32_t* a, uint32_t b0, uint32_t b1) {
    asm volatile("mma.sync.aligned.m16n8k16.row.col.f32.f16.f16.f32 "
                 "{%0,%1,%2,%3}, {%4,%5,%6,%7}, {%8,%9}, {%0,%1,%2,%3};"
                 : "+f"(c[0]), "+f"(c[1]), "+f"(c[2]), "+f"(c[3])
                 : "r"(a[0]), "r"(a[1]), "r"(a[2]), "r"(a[3]), "r"(b0), "r"(b1));
}

__device__ __forceinline__ void cp16(uint32_t s, const void* g) {
    asm volatile("cp.async.cg.shared.global [%0], [%1], 16;" :: "r"(s), "l"(g) : "memory");
}

// ======================= globals (scratch) =======================

__device__ __align__(16) float g_r[2 * DD];
__device__ __align__(16) float g_bo[DD];

__device__ __align__(16) __half g_Gt[2 * DD * DD];   // [512][256] (n-major, k contig)
__device__ __align__(16) __half g_Wt[DD * 2 * DD];   // [256][512]
__device__ __align__(16) __half g_M[(size_t)DN * DD];        // m_last fp16
__device__ __align__(16) __half g_U[(size_t)DN * 2 * DD];    // U fp16
__device__ __align__(16) __half g_Mb[(size_t)DN * 2 * DD];   // aggregated msgs fp16

// ======================= precompute, split by consumer =======================

__global__ void __launch_bounds__(256) prep_g(
    const float* __restrict__ w_in, const float* __restrict__ b_in,
    const float* __restrict__ msgs)
{
    __shared__ float sbuf[512];
    const int b = blockIdx.x;
    const int t = threadIdx.x;

    if (b < 256) {
        const int k0 = b * 2;
        const int h  = k0 >> 8;
        const int d0 = k0 & 255;
        {
            int j = t >> 1, dd = t & 1;
            sbuf[j * 2 + dd] = w_in[(size_t)(DD + h * 128 + j) * DD + d0 + dd];
        }
        __syncthreads();
        const int e = t;
        float a0 = 0.f, a1 = 0.f;
        const float* wq = w_in + (size_t)(h * 128) * DD + e;
#pragma unroll 4
        for (int j = 0; j < 128; j++) {
            float q = wq[(size_t)j * DD];
            a0 = fmaf(q, sbuf[j * 2 + 0], a0);
            a1 = fmaf(q, sbuf[j * 2 + 1], a1);
        }
        g_Gt[(size_t)(k0 + 0) * DD + e] = __float2half_rn(a0);
        g_Gt[(size_t)(k0 + 1) * DD + e] = __float2half_rn(a1);
    } else if (b < 258) {
        int h = b - 256, d = t;
        float a = 0.f;
        for (int j = 0; j < 128; j++)
            a = fmaf(w_in[(size_t)(DD + h * 128 + j) * DD + d], b_in[h * 128 + j], a);
        g_r[h * DD + d] = a;
    } else {
        int idx = (b - 258) * 256 + t;
        int n = idx >> 5, d8 = (idx & 31) * 8;
        const float* gp = msgs + ((size_t)n * DL + (DL - 1)) * DD + d8;
        float4 v0 = *reinterpret_cast<const float4*>(gp);
        float4 v1 = *reinterpret_cast<const float4*>(gp + 4);
        __half2 hh[4];
        hh[0] = __floats2half2_rn(v0.x, v0.y); hh[1] = __floats2half2_rn(v0.z, v0.w);
        hh[2] = __floats2half2_rn(v1.x, v1.y); hh[3] = __floats2half2_rn(v1.z, v1.w);
        *reinterpret_cast<uint4*>(&g_M[(size_t)n * DD + d8]) = *reinterpret_cast<uint4*>(hh);
    }
}

__global__ void __launch_bounds__(256) prep_w(
    const float* __restrict__ w_in, const float* __restrict__ b_in,
    const float* __restrict__ w_out, const float* __restrict__ b_out)
{
    __shared__ float sbuf[256];
    const int b = blockIdx.x;
    const int t = threadIdx.x;

    if (b < 512) {
        const int d = b >> 1;
        const int rep = b & 1;
        if (t < DD) sbuf[t] = w_out[(size_t)d * DD + t];
        __syncthreads();
        const int k = rep * 256 + t;
        const int h = rep, e = t;
        const float* wv  = w_in + (size_t)(2 * DD + h * 128) * DD + e;
        const float* wor = sbuf + h * 128;
        float acc = 0.f;
#pragma unroll 8
        for (int j = 0; j < 128; j++)
            acc = fmaf(wor[j], wv[(size_t)j * DD], acc);
        g_Wt[(size_t)d * 512 + k] = __float2half_rn(acc);
    } else {
        float a = b_out[t];
        for (int c = 0; c < DD; c++)
            a = fmaf(w_out[(size_t)t * DD + c], b_in[2 * DD + c], a);
        g_bo[t] = a;
    }
}

// ======================= HMMA GEMM (3-stage cp.async, interleaved loads) =======================

#define SM_ROW 144
#define SM_BUF 18432             // 128*144
#define STAGE  (2 * SM_BUF)      // 36864 (A, B)
#define GEMM_SMEM (3 * STAGE)    // 110592

template<int KT, bool HALF_OUT>
__device__ __forceinline__ void gemm_body(
    int m_base,
    const __half* __restrict__ A, const __half* __restrict__ B,
    const float* __restrict__ bias, void* __restrict__ Cv, int ldc)
{
    extern __shared__ char sm[];
    const int tid = threadIdx.x, lane = tid & 31, wid = tid >> 5;
    const int m0 = m_base + blockIdx.x * 128, n0 = blockIdx.y * 128;
    const int wm = (wid >> 2) * 64, wn = (wid & 3) * 32;
    const uint32_t sbase = smem_u32(sm);

    float acc[4][4][4];
#pragma unroll
    for (int a = 0; a < 4; a++)
#pragma unroll
        for (int bq = 0; bq < 4; bq++)
#pragma unroll
            for (int cc = 0; cc < 4; cc++) acc[a][bq][cc] = 0.f;

#define LOAD_ITER(st, k0c, it) do { \
        uint32_t s0 = sbase + (st) * STAGE; \
        int idx = tid + (it) * 256; \
        int r = idx >> 3, q = idx & 7; \
        uint32_t so = (uint32_t)(r * SM_ROW + q * 16); \
        size_t ga = (size_t)(m0 + r) * KT + (k0c) + q * 8; \
        size_t gb = (size_t)(n0 + r) * KT + (k0c) + q * 8; \
        cp16(s0 + so, A + ga); \
        cp16(s0 + SM_BUF + so, B + gb); \
    } while (0)

#define LOAD_STAGE(st, k0c) do { \
        LOAD_ITER(st, k0c, 0); LOAD_ITER(st, k0c, 1); \
        LOAD_ITER(st, k0c, 2); LOAD_ITER(st, k0c, 3); \
        asm volatile("cp.async.commit_group;" ::: "memory"); \
    } while (0)

    const int NC = KT / 64;
    LOAD_STAGE(0, 0);
    LOAD_STAGE(1, 64);
    for (int c = 0; c < NC; c++) {
        asm volatile("cp.async.wait_group 1;" ::: "memory");
        __syncthreads();

        const uint32_t uA = sbase + (c % 3) * STAGE;
        const uint32_t uB = uA + SM_BUF;
        const bool do_load = (c + 2 < NC);
        const int  nst = (c + 2) % 3;
        const int  nk0 = (c + 2) * 64;

#pragma unroll
        for (int kk = 0; kk < 4; kk++) {
            const uint32_t colb = (uint32_t)(kk * 32 + (lane >> 4) * 16);
            const uint32_t arow = (uint32_t)(wm + (lane & 15));
            uint32_t af[4][4], bf[2][4];
#pragma unroll
            for (int nt = 0; nt < 2; nt++) {
                uint32_t brow = (uint32_t)(wn + nt * 16 + (lane & 15));
                ldsm4(bf[nt], uB + brow * SM_ROW + colb);
            }
#pragma unroll
            for (int mt = 0; mt < 4; mt++)
                ldsm4(af[mt], uA + (arow + mt * 16) * SM_ROW + colb);
            if (do_load) LOAD_ITER(nst, nk0, kk);
#pragma unroll
            for (int mt = 0; mt < 4; mt++)
#pragma unroll
                for (int ns = 0; ns < 4; ns++)
                    mma16816(acc[mt][ns], af[mt], bf[ns >> 1][ns & 1], bf[ns >> 1][(ns & 1) + 2]);
        }
        asm volatile("cp.async.commit_group;" ::: "memory");
    }
#undef LOAD_STAGE
#undef LOAD_ITER

#pragma unroll
    for (int mt = 0; mt < 4; mt++) {
        int r0 = m0 + wm + mt * 16 + (lane >> 2);
#pragma unroll
        for (int ns = 0; ns < 4; ns++) {
            int cx = n0 + wn + ns * 8 + (lane & 3) * 2;
            float2 bb = *reinterpret_cast<const float2*>(bias + cx);
            float x0 = acc[mt][ns][0] + bb.x, y0 = acc[mt][ns][1] + bb.y;
            float x1 = acc[mt][ns][2] + bb.x, y1 = acc[mt][ns][3] + bb.y;
            if (HALF_OUT) {
                __half* C = reinterpret_cast<__half*>(Cv);
                *reinterpret_cast<__half2*>(C + (size_t)r0 * ldc + cx)       = __floats2half2_rn(x0, y0);
                *reinterpret_cast<__half2*>(C + (size_t)(r0 + 8) * ldc + cx) = __floats2half2_rn(x1, y1);
            } else {
                float* C = reinterpret_cast<float*>(Cv);
                float2 v0; v0.x = x0; v0.y = y0;
                float2 v1; v1.x = x1; v1.y = y1;
                *reinterpret_cast<float2*>(C + (size_t)r0 * ldc + cx) = v0;
                *reinterpret_cast<float2*>(C + (size_t)(r0 + 8) * ldc + cx) = v1;
            }
        }
    }
}

__global__ void __launch_bounds__(256, 2) gemm1_k(int m_base) {
    gemm_body<DD, true>(m_base, g_M, g_Gt, g_r, g_U, 2 * DD);
}
__global__ void __launch_bounds__(256, 2) gemm2_k(float* __restrict__ out, int m_base) {
    gemm_body<2 * DD, false>(m_base, g_Mb, g_Wt, g_bo, out, DD);
}

// ======================= scores + softmax + aggregate =======================
// masked-row skip; batched butterfly reduction (all 20 partials in one pass);
// row l=9 aggregated from fp16 g_M.

__global__ void __launch_bounds__(256) score_agg(
    const float* __restrict__ msgs, const float* __restrict__ tstamp,
    const float* __restrict__ w_time, const float* __restrict__ b_time,
    const int* __restrict__ lengths, int s_base)
{
    int wid = threadIdx.x >> 5, lane = threadIdx.x & 31;
    int s = s_base + blockIdx.x * 8 + wid;

    const int pad = DL - (lengths[s] + 1);   // rows l < pad have zero attention

    const int e8 = lane * 8;
    float wt[8], bt[8], u0[8], u1[8];
    {
        float4 wa = *reinterpret_cast<const float4*>(w_time + e8);
        float4 wb = *reinterpret_cast<const float4*>(w_time + e8 + 4);
        float4 ba = *reinterpret_cast<const float4*>(b_time + e8);
        float4 bb = *reinterpret_cast<const float4*>(b_time + e8 + 4);
        wt[0]=wa.x; wt[1]=wa.y; wt[2]=wa.z; wt[3]=wa.w;
        wt[4]=wb.x; wt[5]=wb.y; wt[6]=wb.z; wt[7]=wb.w;
        bt[0]=ba.x; bt[1]=ba.y; bt[2]=ba.z; bt[3]=ba.w;
        bt[4]=bb.x; bt[5]=bb.y; bt[6]=bb.z; bt[7]=bb.w;
        uint4 h0 = *reinterpret_cast<const uint4*>(&g_U[(size_t)s * 512 + e8]);
        uint4 h1 = *reinterpret_cast<const uint4*>(&g_U[(size_t)s * 512 + 256 + e8]);
        const __half2* p0 = reinterpret_cast<const __half2*>(&h0);
        const __half2* p1 = reinterpret_cast<const __half2*>(&h1);
#pragma unroll
        for (int j = 0; j < 4; j++) {
            float2 f0 = __half22float2(p0[j]);
            float2 f1 = __half22float2(p1[j]);
            u0[2*j] = f0.x; u0[2*j+1] = f0.y;
            u1[2*j] = f1.x; u1[2*j+1] = f1.y;
        }
    }
    float ts9 = tstamp[(size_t)s * DL + (DL - 1)];
    const float scale = 0.08838834764831845f;

    // per-thread partials for all 10 rows x 2 heads (no per-l reduction chains)
    float sc0[DL], sc1[DL];
#pragma unroll
    for (int l = 0; l < DL; l++) {
        if (l >= pad) {
            float delta = tstamp[(size_t)s * DL + l] - ts9;
            float a0 = 0.f, a1 = 0.f;
#pragma unroll
            for (int j = 0; j < 8; j++) {
                float te = __cosf(fmaf(delta, wt[j], bt[j]));
                a0 = fmaf(te, u0[j], a0);
                a1 = fmaf(te, u1[j], a1);
            }
            sc0[l] = a0;
            sc1[l] = a1;
        } else {
            sc0[l] = 0.f;
            sc1[l] = 0.f;
        }
    }
    // one batched butterfly: 20 independent values per step (same order per value)
#pragma unroll
    for (int o = 16; o; o >>= 1) {
#pragma unroll
        for (int l = 0; l < DL; l++) {
            sc0[l] += __shfl_xor_sync(0xFFFFFFFF, sc0[l], o);
            sc1[l] += __shfl_xor_sync(0xFFFFFFFF, sc1[l], o);
        }
    }
#pragma unroll
    for (int l = 0; l < DL; l++) { sc0[l] *= scale; sc1[l] *= scale; }

    float mx0 = -3.4e38f, mx1 = -3.4e38f;
#pragma unroll
    for (int l = 0; l < DL; l++) {
        if (l >= pad) {
            mx0 = fmaxf(mx0, sc0[l]);
            mx1 = fmaxf(mx1, sc1[l]);
        }
    }
    float sm0 = 0.f, sm1 = 0.f;
#pragma unroll
    for (int l = 0; l < DL; l++) {
        if (l >= pad) {
            sc0[l] = __expf(sc0[l] - mx0); sm0 += sc0[l];
            sc1[l] = __expf(sc1[l] - mx1); sm1 += sc1[l];
        }
    }
    float i0 = 1.f / sm0, i1 = 1.f / sm1;
#pragma unroll
    for (int l = 0; l < DL; l++) {
        if (l >= pad) { sc0[l] *= i0; sc1[l] *= i1; }
    }

#pragma unroll
    for (int i = 0; i < 2; i++) {
        int e4 = lane * 4 + i * 128;
        float m0[4] = {0.f, 0.f, 0.f, 0.f};
        float m1[4] = {0.f, 0.f, 0.f, 0.f};
        const float* mp = msgs + (size_t)s * DL * DD + e4;
        // rows pad..8 from fp32 msgs
#pragma unroll
        for (int l = 0; l < DL - 1; l++) {
            if (l >= pad) {
                float4 v = *reinterpret_cast<const float4*>(mp + (size_t)l * DD);
                m0[0] = fmaf(sc0[l], v.x, m0[0]); m0[1] = fmaf(sc0[l], v.y, m0[1]);
                m0[2] = fmaf(sc0[l], v.z, m0[2]); m0[3] = fmaf(sc0[l], v.w, m0[3]);
                m1[0] = fmaf(sc1[l], v.x, m1[0]); m1[1] = fmaf(sc1[l], v.y, m1[1]);
                m1[2] = fmaf(sc1[l], v.z, m1[2]); m1[3] = fmaf(sc1[l], v.w, m1[3]);
            }
        }
        // row 9 (always valid) from fp16 g_M
        {
            uint2 hm = *reinterpret_cast<const uint2*>(&g_M[(size_t)s * DD + e4]);
            const __half2* ph = reinterpret_cast<const __half2*>(&hm);
            float2 f0 = __half22float2(ph[0]);
            float2 f1 = __half22float2(ph[1]);
            float v9[4] = {f0.x, f0.y, f1.x, f1.y};
#pragma unroll
            for (int j = 0; j < 4; j++) {
                m0[j] = fmaf(sc0[DL - 1], v9[j], m0[j]);
                m1[j] = fmaf(sc1[DL - 1], v9[j], m1[j]);
            }
        }
        __half2 h00 = __floats2half2_rn(m0[0], m0[1]);
        __half2 h01 = __floats2half2_rn(m0[2], m0[3]);
        __half2 h10 = __floats2half2_rn(m1[0], m1[1]);
        __half2 h11 = __floats2half2_rn(m1[2], m1[3]);
        *reinterpret_cast<__half2*>(&g_Mb[(size_t)s * 512 + e4])           = h00;
        *reinterpret_cast<__half2*>(&g_Mb[(size_t)s * 512 + e4 + 2])       = h01;
        *reinterpret_cast<__half2*>(&g_Mb[(size_t)s * 512 + 256 + e4])     = h10;
        *reinterpret_cast<__half2*>(&g_Mb[(size_t)s * 512 + 256 + e4 + 2]) = h11;
    }
}

// ======================= streams (created once, pre-checkpoint) =======================

static cudaStream_t g_st[NCHUNK];
static cudaStream_t g_stW;
static cudaEvent_t  g_e0, g_eP, g_eW;
static cudaEvent_t  g_eC[NCHUNK];

namespace {
struct StreamInit {
    StreamInit() {
        for (int i = 0; i < NCHUNK; i++)
            cudaStreamCreateWithFlags(&g_st[i], cudaStreamNonBlocking);
        cudaStreamCreateWithFlags(&g_stW, cudaStreamNonBlocking);
        cudaEventCreateWithFlags(&g_e0, cudaEventDisableTiming);
        cudaEventCreateWithFlags(&g_eP, cudaEventDisableTiming);
        cudaEventCreateWithFlags(&g_eW, cudaEventDisableTiming);
        for (int i = 0; i < NCHUNK; i++)
            cudaEventCreateWithFlags(&g_eC[i], cudaEventDisableTiming);
    }
};
StreamInit g_stream_init;
}

// ======================= launch =======================

extern "C" void kernel_launch(void* const* d_in, const int* in_sizes, int n_in,
                              void* d_out, int out_size) {
    const float* msgs    = (const float*)d_in[0];
    const float* ts      = (const float*)d_in[1];
    const float* w_time  = (const float*)d_in[2];
    const float* b_time  = (const float*)d_in[3];
    const float* w_in    = (const float*)d_in[4];
    const float* b_in    = (const float*)d_in[5];
    const float* w_out   = (const float*)d_in[6];
    const float* b_out   = (const float*)d_in[7];
    const int*   lengths = (const int*)d_in[8];
    float* out = (float*)d_out;

    cudaFuncSetAttribute(gemm1_k, cudaFuncAttributeMaxDynamicSharedMemorySize, GEMM_SMEM);
    cudaFuncSetAttribute(gemm2_k, cudaFuncAttributeMaxDynamicSharedMemorySize, GEMM_SMEM);

    // fork prep_w off the origin stream (gemm2-only deps overlap gemm1/score)
    cudaEventRecord(g_e0, 0);
    cudaStreamWaitEvent(g_stW, g_e0, 0);
    prep_w<<<513, 256, 0, g_stW>>>(w_in, b_in, w_out, b_out);
    cudaEventRecord(g_eW, g_stW);

    // gemm1-critical prep on the origin stream
    prep_g<<<2306, 256>>>(w_in, b_in, msgs);
    cudaEventRecord(g_eP, 0);

    for (int c = 0; c < NCHUNK; c++) {
        const int base = c * CHUNK;
        cudaStreamWaitEvent(g_st[c], g_eP, 0);
        gemm1_k<<<dim3(CHUNK / 128, 4), 256, GEMM_SMEM, g_st[c]>>>(base);
        score_agg<<<CHUNK / 8, 256, 0, g_st[c]>>>(msgs, ts, w_time, b_time, lengths, base);
        cudaStreamWaitEvent(g_st[c], g_eW, 0);
        gemm2_k<<<dim3(CHUNK / 128, 2), 256, GEMM_SMEM, g_st[c]>>>(out, base);
        cudaEventRecord(g_eC[c], g_st[c]);
    }
    for (int c = 0; c < NCHUNK; c++)
        cudaStreamWaitEvent(0, g_eC[c], 0);
}

// round 17
// speedup vs baseline: 1.1225x; 1.0664x over previous
#include <cuda_runtime.h>
#include <cuda_fp16.h>
#include <cstdint>
#include <math.h>

#define DN 16384
#define DL 10
#define DD 256
#define NCHUNK 4
#define CHUNK (DN / NCHUNK)     // 4096

// ======================= helpers =======================

__device__ __forceinline__ uint32_t smem_u32(const void* p) {
    uint32_t a;
    asm("{ .reg .u64 t; cvta.to.shared.u64 t, %1; cvt.u32.u64 %0, t; }" : "=r"(a) : "l"(p));
    return a;
}

__device__ __forceinline__ void ldsm4(uint32_t* r, uint32_t a) {
    asm volatile("ldmatrix.sync.aligned.m8n8.x4.shared.b16 {%0,%1,%2,%3}, [%4];"
                 : "=r"(r[0]), "=r"(r[1]), "=r"(r[2]), "=r"(r[3]) : "r"(a));
}

__device__ __forceinline__ void mma16816(float* c, const uint32_t* a, uint32_t b0, uint32_t b1) {
    asm volatile("mma.sync.aligned.m16n8k16.row.col.f32.f16.f16.f32 "
                 "{%0,%1,%2,%3}, {%4,%5,%6,%7}, {%8,%9}, {%0,%1,%2,%3};"
                 : "+f"(c[0]), "+f"(c[1]), "+f"(c[2]), "+f"(c[3])
                 : "r"(a[0]), "r"(a[1]), "r"(a[2]), "r"(a[3]), "r"(b0), "r"(b1));
}

__device__ __forceinline__ void cp16(uint32_t s, const void* g) {
    asm volatile("cp.async.cg.shared.global [%0], [%1], 16;" :: "r"(s), "l"(g) : "memory");
}

// ======================= globals (scratch) =======================

__device__ __align__(16) float g_r[2 * DD];
__device__ __align__(16) float g_bo[DD];

__device__ __align__(16) __half g_Gt[2 * DD * DD];   // [512][256] (n-major, k contig)
__device__ __align__(16) __half g_Wt[DD * 2 * DD];   // [256][512]
__device__ __align__(16) __half g_M[(size_t)DN * DD];        // m_last fp16
__device__ __align__(16) __half g_U[(size_t)DN * 2 * DD];    // U fp16
__device__ __align__(16) __half g_Mb[(size_t)DN * 2 * DD];   // aggregated msgs fp16

// ======================= precompute, split by consumer =======================

__global__ void __launch_bounds__(256) prep_g(
    const float* __restrict__ w_in, const float* __restrict__ b_in,
    const float* __restrict__ msgs)
{
    __shared__ float sbuf[512];
    const int b = blockIdx.x;
    const int t = threadIdx.x;

    if (b < 256) {
        const int k0 = b * 2;
        const int h  = k0 >> 8;
        const int d0 = k0 & 255;
        {
            int j = t >> 1, dd = t & 1;
            sbuf[j * 2 + dd] = w_in[(size_t)(DD + h * 128 + j) * DD + d0 + dd];
        }
        __syncthreads();
        const int e = t;
        float a0 = 0.f, a1 = 0.f;
        const float* wq = w_in + (size_t)(h * 128) * DD + e;
#pragma unroll 4
        for (int j = 0; j < 128; j++) {
            float q = wq[(size_t)j * DD];
            a0 = fmaf(q, sbuf[j * 2 + 0], a0);
            a1 = fmaf(q, sbuf[j * 2 + 1], a1);
        }
        g_Gt[(size_t)(k0 + 0) * DD + e] = __float2half_rn(a0);
        g_Gt[(size_t)(k0 + 1) * DD + e] = __float2half_rn(a1);
    } else if (b < 258) {
        int h = b - 256, d = t;
        float a = 0.f;
        for (int j = 0; j < 128; j++)
            a = fmaf(w_in[(size_t)(DD + h * 128 + j) * DD + d], b_in[h * 128 + j], a);
        g_r[h * DD + d] = a;
    } else {
        int idx = (b - 258) * 256 + t;
        int n = idx >> 5, d8 = (idx & 31) * 8;
        const float* gp = msgs + ((size_t)n * DL + (DL - 1)) * DD + d8;
        float4 v0 = *reinterpret_cast<const float4*>(gp);
        float4 v1 = *reinterpret_cast<const float4*>(gp + 4);
        __half2 hh[4];
        hh[0] = __floats2half2_rn(v0.x, v0.y); hh[1] = __floats2half2_rn(v0.z, v0.w);
        hh[2] = __floats2half2_rn(v1.x, v1.y); hh[3] = __floats2half2_rn(v1.z, v1.w);
        *reinterpret_cast<uint4*>(&g_M[(size_t)n * DD + d8]) = *reinterpret_cast<uint4*>(hh);
    }
}

__global__ void __launch_bounds__(256) prep_w(
    const float* __restrict__ w_in, const float* __restrict__ b_in,
    const float* __restrict__ w_out, const float* __restrict__ b_out)
{
    __shared__ float sbuf[256];
    const int b = blockIdx.x;
    const int t = threadIdx.x;

    if (b < 512) {
        const int d = b >> 1;
        const int rep = b & 1;
        if (t < DD) sbuf[t] = w_out[(size_t)d * DD + t];
        __syncthreads();
        const int k = rep * 256 + t;
        const int h = rep, e = t;
        const float* wv  = w_in + (size_t)(2 * DD + h * 128) * DD + e;
        const float* wor = sbuf + h * 128;
        float acc = 0.f;
#pragma unroll 8
        for (int j = 0; j < 128; j++)
            acc = fmaf(wor[j], wv[(size_t)j * DD], acc);
        g_Wt[(size_t)d * 512 + k] = __float2half_rn(acc);
    } else {
        float a = b_out[t];
        for (int c = 0; c < DD; c++)
            a = fmaf(w_out[(size_t)t * DD + c], b_in[2 * DD + c], a);
        g_bo[t] = a;
    }
}

// ======================= HMMA GEMM (3-stage cp.async, interleaved loads) =======================

#define SM_ROW 144
#define SM_BUF 18432             // 128*144
#define STAGE  (2 * SM_BUF)      // 36864 (A, B)
#define GEMM_SMEM (3 * STAGE)    // 110592

template<int KT, bool HALF_OUT>
__device__ __forceinline__ void gemm_body(
    int m_base,
    const __half* __restrict__ A, const __half* __restrict__ B,
    const float* __restrict__ bias, void* __restrict__ Cv, int ldc)
{
    extern __shared__ char sm[];
    const int tid = threadIdx.x, lane = tid & 31, wid = tid >> 5;
    const int m0 = m_base + blockIdx.x * 128, n0 = blockIdx.y * 128;
    const int wm = (wid >> 2) * 64, wn = (wid & 3) * 32;
    const uint32_t sbase = smem_u32(sm);

    float acc[4][4][4];
#pragma unroll
    for (int a = 0; a < 4; a++)
#pragma unroll
        for (int bq = 0; bq < 4; bq++)
#pragma unroll
            for (int cc = 0; cc < 4; cc++) acc[a][bq][cc] = 0.f;

#define LOAD_ITER(st, k0c, it) do { \
        uint32_t s0 = sbase + (st) * STAGE; \
        int idx = tid + (it) * 256; \
        int r = idx >> 3, q = idx & 7; \
        uint32_t so = (uint32_t)(r * SM_ROW + q * 16); \
        size_t ga = (size_t)(m0 + r) * KT + (k0c) + q * 8; \
        size_t gb = (size_t)(n0 + r) * KT + (k0c) + q * 8; \
        cp16(s0 + so, A + ga); \
        cp16(s0 + SM_BUF + so, B + gb); \
    } while (0)

#define LOAD_STAGE(st, k0c) do { \
        LOAD_ITER(st, k0c, 0); LOAD_ITER(st, k0c, 1); \
        LOAD_ITER(st, k0c, 2); LOAD_ITER(st, k0c, 3); \
        asm volatile("cp.async.commit_group;" ::: "memory"); \
    } while (0)

    const int NC = KT / 64;
    LOAD_STAGE(0, 0);
    LOAD_STAGE(1, 64);
    for (int c = 0; c < NC; c++) {
        asm volatile("cp.async.wait_group 1;" ::: "memory");
        __syncthreads();

        const uint32_t uA = sbase + (c % 3) * STAGE;
        const uint32_t uB = uA + SM_BUF;
        const bool do_load = (c + 2 < NC);
        const int  nst = (c + 2) % 3;
        const int  nk0 = (c + 2) * 64;

#pragma unroll
        for (int kk = 0; kk < 4; kk++) {
            const uint32_t colb = (uint32_t)(kk * 32 + (lane >> 4) * 16);
            const uint32_t arow = (uint32_t)(wm + (lane & 15));
            uint32_t af[4][4], bf[2][4];
#pragma unroll
            for (int nt = 0; nt < 2; nt++) {
                uint32_t brow = (uint32_t)(wn + nt * 16 + (lane & 15));
                ldsm4(bf[nt], uB + brow * SM_ROW + colb);
            }
#pragma unroll
            for (int mt = 0; mt < 4; mt++)
                ldsm4(af[mt], uA + (arow + mt * 16) * SM_ROW + colb);
            if (do_load) LOAD_ITER(nst, nk0, kk);
#pragma unroll
            for (int mt = 0; mt < 4; mt++)
#pragma unroll
                for (int ns = 0; ns < 4; ns++)
                    mma16816(acc[mt][ns], af[mt], bf[ns >> 1][ns & 1], bf[ns >> 1][(ns & 1) + 2]);
        }
        asm volatile("cp.async.commit_group;" ::: "memory");
    }
#undef LOAD_STAGE
#undef LOAD_ITER

#pragma unroll
    for (int mt = 0; mt < 4; mt++) {
        int r0 = m0 + wm + mt * 16 + (lane >> 2);
#pragma unroll
        for (int ns = 0; ns < 4; ns++) {
            int cx = n0 + wn + ns * 8 + (lane & 3) * 2;
            float2 bb = *reinterpret_cast<const float2*>(bias + cx);
            float x0 = acc[mt][ns][0] + bb.x, y0 = acc[mt][ns][1] + bb.y;
            float x1 = acc[mt][ns][2] + bb.x, y1 = acc[mt][ns][3] + bb.y;
            if (HALF_OUT) {
                __half* C = reinterpret_cast<__half*>(Cv);
                *reinterpret_cast<__half2*>(C + (size_t)r0 * ldc + cx)       = __floats2half2_rn(x0, y0);
                *reinterpret_cast<__half2*>(C + (size_t)(r0 + 8) * ldc + cx) = __floats2half2_rn(x1, y1);
            } else {
                float* C = reinterpret_cast<float*>(Cv);
                float2 v0; v0.x = x0; v0.y = y0;
                float2 v1; v1.x = x1; v1.y = y1;
                *reinterpret_cast<float2*>(C + (size_t)r0 * ldc + cx) = v0;
                *reinterpret_cast<float2*>(C + (size_t)(r0 + 8) * ldc + cx) = v1;
            }
        }
    }
}

__global__ void __launch_bounds__(256, 2) gemm1_k(int m_base) {
    gemm_body<DD, true>(m_base, g_M, g_Gt, g_r, g_U, 2 * DD);
}
__global__ void __launch_bounds__(256, 2) gemm2_k(float* __restrict__ out, int m_base) {
    gemm_body<2 * DD, false>(m_base, g_Mb, g_Wt, g_bo, out, DD);
}

// ======================= scores + softmax + aggregate =======================
// masked-row skip; batched butterfly reduction; row l=9 from fp16 g_M.

__global__ void __launch_bounds__(256) score_agg(
    const float* __restrict__ msgs, const float* __restrict__ tstamp,
    const float* __restrict__ w_time, const float* __restrict__ b_time,
    const int* __restrict__ lengths, int s_base)
{
    int wid = threadIdx.x >> 5, lane = threadIdx.x & 31;
    int s = s_base + blockIdx.x * 8 + wid;

    const int pad = DL - (lengths[s] + 1);   // rows l < pad have zero attention

    const int e8 = lane * 8;
    float wt[8], bt[8], u0[8], u1[8];
    {
        float4 wa = *reinterpret_cast<const float4*>(w_time + e8);
        float4 wb = *reinterpret_cast<const float4*>(w_time + e8 + 4);
        float4 ba = *reinterpret_cast<const float4*>(b_time + e8);
        float4 bb = *reinterpret_cast<const float4*>(b_time + e8 + 4);
        wt[0]=wa.x; wt[1]=wa.y; wt[2]=wa.z; wt[3]=wa.w;
        wt[4]=wb.x; wt[5]=wb.y; wt[6]=wb.z; wt[7]=wb.w;
        bt[0]=ba.x; bt[1]=ba.y; bt[2]=ba.z; bt[3]=ba.w;
        bt[4]=bb.x; bt[5]=bb.y; bt[6]=bb.z; bt[7]=bb.w;
        uint4 h0 = *reinterpret_cast<const uint4*>(&g_U[(size_t)s * 512 + e8]);
        uint4 h1 = *reinterpret_cast<const uint4*>(&g_U[(size_t)s * 512 + 256 + e8]);
        const __half2* p0 = reinterpret_cast<const __half2*>(&h0);
        const __half2* p1 = reinterpret_cast<const __half2*>(&h1);
#pragma unroll
        for (int j = 0; j < 4; j++) {
            float2 f0 = __half22float2(p0[j]);
            float2 f1 = __half22float2(p1[j]);
            u0[2*j] = f0.x; u0[2*j+1] = f0.y;
            u1[2*j] = f1.x; u1[2*j+1] = f1.y;
        }
    }
    float ts9 = tstamp[(size_t)s * DL + (DL - 1)];
    const float scale = 0.08838834764831845f;

    // per-thread partials for all 10 rows x 2 heads (no per-l reduction chains)
    float sc0[DL], sc1[DL];
#pragma unroll
    for (int l = 0; l < DL; l++) {
        if (l >= pad) {
            float delta = tstamp[(size_t)s * DL + l] - ts9;
            float a0 = 0.f, a1 = 0.f;
#pragma unroll
            for (int j = 0; j < 8; j++) {
                float te = __cosf(fmaf(delta, wt[j], bt[j]));
                a0 = fmaf(te, u0[j], a0);
                a1 = fmaf(te, u1[j], a1);
            }
            sc0[l] = a0;
            sc1[l] = a1;
        } else {
            sc0[l] = 0.f;
            sc1[l] = 0.f;
        }
    }
    // one batched butterfly: 20 independent values per step (same order per value)
#pragma unroll
    for (int o = 16; o; o >>= 1) {
#pragma unroll
        for (int l = 0; l < DL; l++) {
            sc0[l] += __shfl_xor_sync(0xFFFFFFFF, sc0[l], o);
            sc1[l] += __shfl_xor_sync(0xFFFFFFFF, sc1[l], o);
        }
    }
#pragma unroll
    for (int l = 0; l < DL; l++) { sc0[l] *= scale; sc1[l] *= scale; }

    float mx0 = -3.4e38f, mx1 = -3.4e38f;
#pragma unroll
    for (int l = 0; l < DL; l++) {
        if (l >= pad) {
            mx0 = fmaxf(mx0, sc0[l]);
            mx1 = fmaxf(mx1, sc1[l]);
        }
    }
    float sm0 = 0.f, sm1 = 0.f;
#pragma unroll
    for (int l = 0; l < DL; l++) {
        if (l >= pad) {
            sc0[l] = __expf(sc0[l] - mx0); sm0 += sc0[l];
            sc1[l] = __expf(sc1[l] - mx1); sm1 += sc1[l];
        }
    }
    float i0 = 1.f / sm0, i1 = 1.f / sm1;
#pragma unroll
    for (int l = 0; l < DL; l++) {
        if (l >= pad) { sc0[l] *= i0; sc1[l] *= i1; }
    }

#pragma unroll
    for (int i = 0; i < 2; i++) {
        int e4 = lane * 4 + i * 128;
        float m0[4] = {0.f, 0.f, 0.f, 0.f};
        float m1[4] = {0.f, 0.f, 0.f, 0.f};
        const float* mp = msgs + (size_t)s * DL * DD + e4;
        // rows pad..8 from fp32 msgs
#pragma unroll
        for (int l = 0; l < DL - 1; l++) {
            if (l >= pad) {
                float4 v = *reinterpret_cast<const float4*>(mp + (size_t)l * DD);
                m0[0] = fmaf(sc0[l], v.x, m0[0]); m0[1] = fmaf(sc0[l], v.y, m0[1]);
                m0[2] = fmaf(sc0[l], v.z, m0[2]); m0[3] = fmaf(sc0[l], v.w, m0[3]);
                m1[0] = fmaf(sc1[l], v.x, m1[0]); m1[1] = fmaf(sc1[l], v.y, m1[1]);
                m1[2] = fmaf(sc1[l], v.z, m1[2]); m1[3] = fmaf(sc1[l], v.w, m1[3]);
            }
        }
        // row 9 (always valid) from fp16 g_M
        {
            uint2 hm = *reinterpret_cast<const uint2*>(&g_M[(size_t)s * DD + e4]);
            const __half2* ph = reinterpret_cast<const __half2*>(&hm);
            float2 f0 = __half22float2(ph[0]);
            float2 f1 = __half22float2(ph[1]);
            float v9[4] = {f0.x, f0.y, f1.x, f1.y};
#pragma unroll
            for (int j = 0; j < 4; j++) {
                m0[j] = fmaf(sc0[DL - 1], v9[j], m0[j]);
                m1[j] = fmaf(sc1[DL - 1], v9[j], m1[j]);
            }
        }
        __half2 h00 = __floats2half2_rn(m0[0], m0[1]);
        __half2 h01 = __floats2half2_rn(m0[2], m0[3]);
        __half2 h10 = __floats2half2_rn(m1[0], m1[1]);
        __half2 h11 = __floats2half2_rn(m1[2], m1[3]);
        *reinterpret_cast<__half2*>(&g_Mb[(size_t)s * 512 + e4])           = h00;
        *reinterpret_cast<__half2*>(&g_Mb[(size_t)s * 512 + e4 + 2])       = h01;
        *reinterpret_cast<__half2*>(&g_Mb[(size_t)s * 512 + 256 + e4])     = h10;
        *reinterpret_cast<__half2*>(&g_Mb[(size_t)s * 512 + 256 + e4 + 2]) = h11;
    }
}

// ======================= streams (created once, pre-checkpoint) =======================

static cudaStream_t g_st[NCHUNK];
static cudaStream_t g_stW;
static cudaEvent_t  g_e0, g_eP, g_eW;
static cudaEvent_t  g_eC[NCHUNK];

namespace {
struct StreamInit {
    StreamInit() {
        for (int i = 0; i < NCHUNK; i++)
            cudaStreamCreateWithFlags(&g_st[i], cudaStreamNonBlocking);
        cudaStreamCreateWithFlags(&g_stW, cudaStreamNonBlocking);
        cudaEventCreateWithFlags(&g_e0, cudaEventDisableTiming);
        cudaEventCreateWithFlags(&g_eP, cudaEventDisableTiming);
        cudaEventCreateWithFlags(&g_eW, cudaEventDisableTiming);
        for (int i = 0; i < NCHUNK; i++)
            cudaEventCreateWithFlags(&g_eC[i], cudaEventDisableTiming);
    }
};
StreamInit g_stream_init;
}

// ======================= launch =======================

extern "C" void kernel_launch(void* const* d_in, const int* in_sizes, int n_in,
                              void* d_out, int out_size) {
    const float* msgs    = (const float*)d_in[0];
    const float* ts      = (const float*)d_in[1];
    const float* w_time  = (const float*)d_in[2];
    const float* b_time  = (const float*)d_in[3];
    const float* w_in    = (const float*)d_in[4];
    const float* b_in    = (const float*)d_in[5];
    const float* w_out   = (const float*)d_in[6];
    const float* b_out   = (const float*)d_in[7];
    const int*   lengths = (const int*)d_in[8];
    float* out = (float*)d_out;

    cudaFuncSetAttribute(gemm1_k, cudaFuncAttributeMaxDynamicSharedMemorySize, GEMM_SMEM);
    cudaFuncSetAttribute(gemm2_k, cudaFuncAttributeMaxDynamicSharedMemorySize, GEMM_SMEM);

    // fork prep_w off the origin stream (gemm2-only deps overlap gemm1/score)
    cudaEventRecord(g_e0, 0);
    cudaStreamWaitEvent(g_stW, g_e0, 0);
    prep_w<<<513, 256, 0, g_stW>>>(w_in, b_in, w_out, b_out);
    cudaEventRecord(g_eW, g_stW);

    // gemm1-critical prep on the origin stream
    prep_g<<<2306, 256>>>(w_in, b_in, msgs);
    cudaEventRecord(g_eP, 0);

    for (int c = 0; c < NCHUNK; c++) {
        const int base = c * CHUNK;
        cudaStreamWaitEvent(g_st[c], g_eP, 0);
        gemm1_k<<<dim3(CHUNK / 128, 4), 256, GEMM_SMEM, g_st[c]>>>(base);
        score_agg<<<CHUNK / 8, 256, 0, g_st[c]>>>(msgs, ts, w_time, b_time, lengths, base);
        cudaStreamWaitEvent(g_st[c], g_eW, 0);
        gemm2_k<<<dim3(CHUNK / 128, 2), 256, GEMM_SMEM, g_st[c]>>>(out, base);
        cudaEventRecord(g_eC[c], g_st[c]);
    }
    for (int c = 0; c < NCHUNK; c++)
        cudaStreamWaitEvent(0, g_eC[c], 0);
}